// round 4
// baseline (speedup 1.0000x reference)
#include <cuda_runtime.h>
#include <math.h>

#define BB 16
#define AA 8400
#define MM 64
#define NCC 80
#define TOPK_K 10
#define EPS_G 1e-9f
#define EPS_C 1e-7f
#define WSTRIDE 12             // winners per gt: 10 topk + 1 quirk + pad

// -------- scratch (device globals; no allocation allowed) --------
__device__ int g_win[BB * MM * WSTRIDE];           // winner anchors, -1 = empty
__device__ unsigned long long g_bits[BB * AA];     // claim bits (bit m)
__device__ int g_posal[BB * MM];                   // pos_align   (float bits, >=0)
__device__ int g_posov[BB * MM];                   // pos_overlap (float bits, >=0)
__device__ float g_num[BB * AA];                   // align at (tgt,a), claimed only
__device__ int g_pack[BB * AA];                    // tgt | lab<<6, claimed only

__device__ __forceinline__ float ciou_full(float gx1, float gy1, float gx2, float gy2,
                                           float px1, float py1, float px2, float py2)
{
    const float w1 = gx2 - gx1;
    const float h1 = gy2 - gy1 + EPS_C;
    const float w2 = px2 - px1;
    const float h2 = py2 - py1 + EPS_C;
    const float iw = fminf(gx2, px2) - fmaxf(gx1, px1);
    const float ih = fminf(gy2, py2) - fmaxf(gy1, py1);
    const float inter = fmaxf(iw, 0.0f) * fmaxf(ih, 0.0f);
    const float uni = w1 * h1 + w2 * h2 - inter + EPS_C;
    const float iou = inter / uni;
    const float cw = fmaxf(gx2, px2) - fminf(gx1, px1);
    const float ch = fmaxf(gy2, py2) - fminf(gy1, py1);
    const float c2 = cw * cw + ch * ch + EPS_C;
    const float dx = px1 + px2 - gx1 - gx2;
    const float dy = py1 + py2 - gy1 - gy2;
    const float rho2 = (dx * dx + dy * dy) * 0.25f;
    const float dat = atanf(w2 / h2) - atanf(w1 / h1);
    const float v = (4.0f / (float)(M_PI * M_PI)) * dat * dat;
    const float alpha = v / (v - iou + (1.0f + EPS_C));
    return iou - (rho2 / c2 + v * alpha);
}

// ---------------- K0: defaults + zero (pure bandwidth) ----------------
__global__ void __launch_bounds__(256)
fill_kernel(const float* __restrict__ gt_bboxes,
            float* __restrict__ out_bboxes,
            float* __restrict__ out_scores,
            float* __restrict__ out_fg)
{
    const int idx = blockIdx.x * 256 + threadIdx.x;
    const int nthr = gridDim.x * 256;
    const float4 z4 = make_float4(0.0f, 0.0f, 0.0f, 0.0f);

    // zero all scores: B*A*NC/4 float4
    float4* s4 = (float4*)out_scores;
    const int ns4 = BB * AA * NCC / 4;
    for (int k = idx; k < ns4; k += nthr) s4[k] = z4;

    // defaults for bbox/fg + zero claim bits
    if (idx < BB * AA) {
        const int b = idx / AA;
        ((float4*)out_bboxes)[idx] = ((const float4*)gt_bboxes)[b * MM];
        out_fg[idx] = 0.0f;
        g_bits[idx] = 0ull;
    }
}

// ---------------- K1: warp-per-gt enumerate + register top-k ----------------
__global__ void __launch_bounds__(128)
phase1_kernel(const float* __restrict__ pd_scores,
              const float* __restrict__ pd_bboxes,
              const int* __restrict__ gt_labels,
              const float* __restrict__ gt_bboxes,
              const float* __restrict__ mask_gt)
{
    const int wid_in_blk = threadIdx.x >> 5;
    const int lane = threadIdx.x & 31;
    const int bm = blockIdx.x * 4 + wid_in_blk;   // 256 blocks x 4 warps
    const int b = bm >> 6;
    const int m = bm & 63;

    if (lane == 0) { g_posal[bm] = 0; g_posov[bm] = 0; }

    const float4 gb = ((const float4*)gt_bboxes)[bm];
    const float gx1 = gb.x, gy1 = gb.y, gx2 = gb.z, gy2 = gb.w;
    const int   label = gt_labels[bm];
    const bool  valid = mask_gt[bm] > 0.0f;

    const float w1 = gx2 - gx1;
    const float h1 = gy2 - gy1 + EPS_C;
    const float area1 = w1 * h1;
    const float at1 = atanf(w1 / h1);
    const float inv_pi2_4 = 4.0f / (float)(M_PI * M_PI);

    const float4* pb = (const float4*)(pd_bboxes + (size_t)b * AA * 4);
    const float*  ps = pd_scores + (size_t)b * AA * NCC;

    // anchor lattice: level L has n=640/s points per axis at ((c+0.5)*s)
    const int   Lbase[3] = {0, 6400, 8000};
    const int   Ln[3]    = {80, 40, 20};
    const float Lsf[3]   = {8.0f, 16.0f, 32.0f};

    int cmin[3], rmin[3], Wd[3], cum[4];
    cum[0] = 0;
#pragma unroll
    for (int L = 0; L < 3; L++) {
        int c0 = 0, c1 = -1, r0 = 0, r1 = -1;
        if (valid) {
            const float inv_s = 1.0f / Lsf[L];
            c0 = max(0, (int)floorf(gx1 * inv_s) - 1);
            c1 = min(Ln[L] - 1, (int)ceilf(gx2 * inv_s));
            r0 = max(0, (int)floorf(gy1 * inv_s) - 1);
            r1 = min(Ln[L] - 1, (int)ceilf(gy2 * inv_s));
        }
        const int w = c1 - c0 + 1;
        const int h = r1 - r0 + 1;
        const int cnt = (w > 0 && h > 0) ? w * h : 0;
        cmin[L] = c0; rmin[L] = r0; Wd[L] = (w > 0) ? w : 1;
        cum[L + 1] = cum[L] + cnt;
    }
    const int T = cum[3];

    // per-lane register top-10 (desc sorted), key = met_bits<<32 | ~a
    unsigned long long top[TOPK_K];
#pragma unroll
    for (int k = 0; k < TOPK_K; k++) top[k] = 0ull;

    for (int t = lane; t < T; t += 32) {
        const int L = (t < cum[1]) ? 0 : ((t < cum[2]) ? 1 : 2);
        const int local = t - cum[L];
        const int row = rmin[L] + local / Wd[L];
        const int col = cmin[L] + local - (local / Wd[L]) * Wd[L];
        const float s = Lsf[L];
        const float ax = ((float)col + 0.5f) * s;   // bit-exact vs anc input
        const float ay = ((float)row + 0.5f) * s;
        const float d = fminf(fminf(ax - gx1, ay - gy1), fminf(gx2 - ax, gy2 - ay));
        if (!(d > EPS_G)) continue;
        const int a = Lbase[L] + row * Ln[L] + col;
        const float4 p = pb[a];
        const float w2 = p.z - p.x;
        const float h2 = p.w - p.y + EPS_C;
        const float iw = fminf(gx2, p.z) - fmaxf(gx1, p.x);
        const float ih = fminf(gy2, p.w) - fmaxf(gy1, p.y);
        const float inter = fmaxf(iw, 0.0f) * fmaxf(ih, 0.0f);
        const float uni = area1 + w2 * h2 - inter + EPS_C;
        const float iou = inter / uni;
        const float cw = fmaxf(gx2, p.z) - fminf(gx1, p.x);
        const float ch = fmaxf(gy2, p.w) - fminf(gy1, p.y);
        const float c2 = cw * cw + ch * ch + EPS_C;
        const float dx = p.x + p.z - gx1 - gx2;
        const float dy = p.y + p.w - gy1 - gy2;
        const float rho2 = (dx * dx + dy * dy) * 0.25f;
        const float dat = atanf(w2 / h2) - at1;
        const float v = inv_pi2_4 * dat * dat;
        const float alpha = v / (v - iou + (1.0f + EPS_C));
        const float ciou = iou - (rho2 / c2 + v * alpha);
        const float ovl = fmaxf(ciou, 0.0f);
        if (ovl <= 0.0f) continue;
        const float sc = ps[(size_t)a * NCC + label];
        const float o2 = ovl * ovl;
        const float met = sqrtf(sc) * (o2 * o2 * o2);
        if (met > EPS_G) {
            const unsigned long long key =
                ((unsigned long long)__float_as_uint(met) << 32)
                | (unsigned long long)(0xFFFFFFFFu - (unsigned)a);
            if (key > top[TOPK_K - 1]) {
                top[TOPK_K - 1] = key;
#pragma unroll
                for (int k = TOPK_K - 1; k > 0; k--) {
                    if (top[k] > top[k - 1]) {
                        const unsigned long long tm = top[k - 1];
                        top[k - 1] = top[k];
                        top[k] = tm;
                    }
                }
            }
        }
    }

    // merge: 10 rounds of warp argmax over each lane's current head
    int kept = 0;
    const unsigned full = 0xffffffffu;
    for (int r = 0; r < TOPK_K; r++) {
        unsigned long long bk = top[0];
        int bl = lane;
#pragma unroll
        for (int off = 16; off; off >>= 1) {
            const unsigned long long ok = __shfl_down_sync(full, bk, off);
            const int ol = __shfl_down_sync(full, bl, off);
            if (ok > bk) { bk = ok; bl = ol; }
        }
        bk = __shfl_sync(full, bk, 0);
        bl = __shfl_sync(full, bl, 0);
        const float wv = __uint_as_float((unsigned)(bk >> 32));
        if (wv <= EPS_G) break;
        if (lane == 0) {
            const int a = (int)(0xFFFFFFFFu - (unsigned)(bk & 0xFFFFFFFFu));
            g_win[bm * WSTRIDE + kept] = a;
            atomicOr(&g_bits[(size_t)b * AA + a], 1ull << m);
        }
        if (lane == bl) {
#pragma unroll
            for (int k = 0; k < TOPK_K - 1; k++) top[k] = top[k + 1];
            top[TOPK_K - 1] = 0ull;
        }
        kept++;
    }

    if (lane == 0) {
        // reference quirk: dropped top-k slots scatter into anchor 0,
        // gated by mask_in_gts[0] & mask_pos_gt[0]
        if (kept < TOPK_K) {
            const float d0 = fminf(fminf(4.0f - gx1, 4.0f - gy1),
                                   fminf(gx2 - 4.0f, gy2 - 4.0f));
            if (valid && d0 > EPS_G) {
                g_win[bm * WSTRIDE + kept] = 0;
                atomicOr(&g_bits[(size_t)b * AA], 1ull << m);
                kept++;
            }
        }
        for (int k = kept; k < WSTRIDE; k++) g_win[bm * WSTRIDE + k] = -1;
    }
}

// ---------------- K2: sparse resolve over claimed anchors ----------------
__global__ void __launch_bounds__(256)
resolve_kernel(const float* __restrict__ pd_scores,
               const float* __restrict__ pd_bboxes,
               const float* __restrict__ anc,
               const int* __restrict__ gt_labels,
               const float* __restrict__ gt_bboxes,
               const float* __restrict__ mask_gt,
               float* __restrict__ out_bboxes,
               float* __restrict__ out_fg)
{
    const int j = blockIdx.x * 256 + threadIdx.x;
    if (j >= BB * MM * WSTRIDE) return;
    const int bm = j / WSTRIDE;
    const int b = bm >> 6;
    const int m = bm & 63;
    const int a = g_win[j];
    if (a < 0) return;

    const size_t i = (size_t)b * AA + a;
    const unsigned long long bits = g_bits[i];
    if (m != __ffsll((long long)bits) - 1) return;   // owner = lowest claiming gt

    const float2 an = ((const float2*)anc)[a];
    const float4 p = ((const float4*)pd_bboxes)[i];

    int tgt;
    if (__popcll(bits) == 1) {
        tgt = m;
    } else {
        // argmax over ALL m of masked clipped CIoU (first max wins)
        float best = -1.0f;
        int bi = 0;
        for (int mm = 0; mm < MM; mm++) {
            float v = 0.0f;
            if (mask_gt[b * MM + mm] > 0.0f) {
                const float4 g = ((const float4*)gt_bboxes)[b * MM + mm];
                const float d = fminf(fminf(an.x - g.x, an.y - g.y),
                                      fminf(g.z - an.x, g.w - an.y));
                if (d > EPS_G) {
                    const float c = ciou_full(g.x, g.y, g.z, g.w, p.x, p.y, p.z, p.w);
                    v = fmaxf(c, 0.0f);
                }
            }
            if (v > best) { best = v; bi = mm; }
        }
        tgt = bi;
    }

    const float4 g = ((const float4*)gt_bboxes)[b * MM + tgt];
    float ovl = 0.0f, num = 0.0f;
    bool pos = false;
    if (mask_gt[b * MM + tgt] > 0.0f) {
        const float d = fminf(fminf(an.x - g.x, an.y - g.y),
                              fminf(g.z - an.x, g.w - an.y));
        pos = d > EPS_G;
    }
    if (pos) {
        const float c = ciou_full(g.x, g.y, g.z, g.w, p.x, p.y, p.z, p.w);
        ovl = fmaxf(c, 0.0f);
        const int lb = gt_labels[b * MM + tgt];
        const float sc = pd_scores[i * NCC + lb];
        const float o2 = ovl * ovl;
        num = sqrtf(sc) * (o2 * o2 * o2);
    }
    atomicMax(&g_posal[b * MM + tgt], __float_as_int(num));
    atomicMax(&g_posov[b * MM + tgt], __float_as_int(ovl));

    int lab = gt_labels[b * MM + tgt];
    if (lab < 0) lab = 0;
    g_num[i] = num;
    g_pack[i] = tgt | (lab << 6);
    ((float4*)out_bboxes)[i] = g;
    out_fg[i] = 1.0f;
}

// ---------------- K3: sparse norm -> score scatter ----------------
__global__ void __launch_bounds__(256)
finalize_kernel(float* __restrict__ out_scores)
{
    const int j = blockIdx.x * 256 + threadIdx.x;
    if (j >= BB * MM * WSTRIDE) return;
    const int bm = j / WSTRIDE;
    const int b = bm >> 6;
    const int m = bm & 63;
    const int a = g_win[j];
    if (a < 0) return;

    const size_t i = (size_t)b * AA + a;
    const unsigned long long bits = g_bits[i];
    if (m != __ffsll((long long)bits) - 1) return;

    const int pk = g_pack[i];
    const int tgt = pk & 63;
    const int lab = (pk >> 6) & 127;
    const float pa = __int_as_float(g_posal[b * MM + tgt]);
    const float po = __int_as_float(g_posov[b * MM + tgt]);
    const float norm = g_num[i] * po / (pa + EPS_G);
    out_scores[i * NCC + lab] = norm;
}

extern "C" void kernel_launch(void* const* d_in, const int* in_sizes, int n_in,
                              void* d_out, int out_size)
{
    const float* pd_scores = (const float*)d_in[0];   // (B, A, NC) f32
    const float* pd_bboxes = (const float*)d_in[1];   // (B, A, 4)  f32
    const float* anc       = (const float*)d_in[2];   // (A, 2)     f32
    const int*   gt_labels = (const int*)  d_in[3];   // (B, M, 1)  i32
    const float* gt_bboxes = (const float*)d_in[4];   // (B, M, 4)  f32
    const float* mask_gt   = (const float*)d_in[5];   // (B, M, 1)  f32

    float* out = (float*)d_out;
    float* out_bboxes = out;                                  // B*A*4
    float* out_scores = out + (size_t)BB * AA * 4;            // B*A*NC
    float* out_fg     = out + (size_t)BB * AA * (4 + NCC);    // B*A

    fill_kernel<<<1332, 256>>>(gt_bboxes, out_bboxes, out_scores, out_fg);
    phase1_kernel<<<BB * MM / 4, 128>>>(pd_scores, pd_bboxes,
                                        gt_labels, gt_bboxes, mask_gt);
    const int nW = BB * MM * WSTRIDE;
    resolve_kernel<<<(nW + 255) / 256, 256>>>(pd_scores, pd_bboxes, anc,
                                              gt_labels, gt_bboxes, mask_gt,
                                              out_bboxes, out_fg);
    finalize_kernel<<<(nW + 255) / 256, 256>>>(out_scores);
}